// round 9
// baseline (speedup 1.0000x reference)
#include <cuda_runtime.h>
#include <cuda_bf16.h>
#include <cstdint>
#include <cstddef>

#define DB 4
#define DE 16
#define DN 1024
#define DD 512
#define NBE (DB * DE)

// Scratch (allocation-free rule: __device__ globals)
__device__ __align__(256) float g_q[(size_t)NBE * DN * DD];
__device__ __align__(256) float g_k[(size_t)NBE * DN * DD];
__device__ __align__(256) float g_v[(size_t)NBE * DN * DD];
__device__ __align__(256) float g_att[(size_t)NBE * DD * DD];

// ---------------- helpers ----------------
__device__ __forceinline__ uint32_t smem_u32(const void* p) {
    uint32_t a;
    asm("{ .reg .u64 t; cvta.to.shared.u64 t, %1; cvt.u32.u64 %0, t; }" : "=r"(a) : "l"(p));
    return a;
}
__device__ __forceinline__ void ldsm4(uint32_t* r, uint32_t addr) {
    asm volatile("ldmatrix.sync.aligned.m8n8.x4.shared.b16 {%0,%1,%2,%3}, [%4];"
                 : "=r"(r[0]), "=r"(r[1]), "=r"(r[2]), "=r"(r[3]) : "r"(addr));
}
__device__ __forceinline__ void ldsm4t(uint32_t* r, uint32_t addr) {
    asm volatile("ldmatrix.sync.aligned.m8n8.x4.trans.shared.b16 {%0,%1,%2,%3}, [%4];"
                 : "=r"(r[0]), "=r"(r[1]), "=r"(r[2]), "=r"(r[3]) : "r"(addr));
}
__device__ __forceinline__ void mma16816(float* d, const uint32_t* a, const uint32_t* b) {
    asm volatile(
        "mma.sync.aligned.m16n8k16.row.col.f32.bf16.bf16.f32 "
        "{%0,%1,%2,%3}, {%4,%5,%6,%7}, {%8,%9}, {%0,%1,%2,%3};"
        : "+f"(d[0]), "+f"(d[1]), "+f"(d[2]), "+f"(d[3])
        : "r"(a[0]), "r"(a[1]), "r"(a[2]), "r"(a[3]), "r"(b[0]), "r"(b[1]));
}
// split (x,y) fp32 -> hi bf16x2 + lo bf16x2
__device__ __forceinline__ void split2(float x, float y, uint32_t& h, uint32_t& l) {
    __nv_bfloat162 hb = __floats2bfloat162_rn(x, y);
    float2 hf = __bfloat1622float2(hb);
    __nv_bfloat162 lb = __floats2bfloat162_rn(x - hf.x, y - hf.y);
    h = reinterpret_cast<uint32_t&>(hb);
    l = reinterpret_cast<uint32_t&>(lb);
}

// SMEM layout per stage (bytes):
//   Ahi [128][40 bf16] stride 80B : 10240
//   Alo                           : 10240
//   Bhi [32 k][256 n bf16] 512B rows, xor-swz : 16384
//   Blo                                       : 16384
static constexpr int AHI = 0;
static constexpr int ALO = 10240;
static constexpr int BHI = 20480;
static constexpr int BLO = 36864;
static constexpr int STG = 53248;
static constexpr int SMEM_REQ = 2 * STG;   // 104 KB

// ---------------------------------------------------------------------------
// HMMA bf16-split GEMM. CTA tile 128(M) x 256(N), BK=32, 256 thr,
// 8 warps in 2(M) x 4(N), each computing a 64x64 warp tile.
// TRANSA=false: C[m,n] = sum_k A[m,k] B[k,n]   (A row-major M x K)
// TRANSA=true : C[m,n] = sum_k A[k,m] B[k,n]   (A row-major K x M)
// B row-major K x N. Batch: A += be*sA ; B += (be%modB)*sB ; C += be*sC
// ---------------------------------------------------------------------------
template <bool TRANSA>
__global__ __launch_bounds__(256, 1) void hmma_gemm(
    const float* __restrict__ Ab, const float* __restrict__ Bb, float* __restrict__ Cb,
    int lda, int ldb, int ldc, long sA, long sB, long sC, int modB, int ktiles, int ntile)
{
    extern __shared__ __align__(1024) char smem[];
    const uint32_t sbase = smem_u32(smem);

    const int t    = threadIdx.x;
    const int lane = t & 31;
    const int wid  = t >> 5;
    const int be   = blockIdx.y;
    const float* A = Ab + (size_t)be * sA;
    const float* B = Bb + (size_t)(be % modB) * sB;
    float*       C = Cb + (size_t)be * sC;

    const int m0 = (blockIdx.x / ntile) << 7;
    const int n0 = (blockIdx.x % ntile) << 8;

    // ---- loader index maps ----
    const int bk = t >> 3;             // B: k row 0..31
    const int bn = (t & 7) << 5;       // B: n start (32 floats per thread)
    const float* Bptr = B + (size_t)bk * ldb + n0 + bn;

    const int am  = t >> 1;            // A no-trans: m row
    const int akc = (t & 1) << 4;      // A no-trans: k start (16 floats)
    const int akp = t & 15;            // A trans: k-pair -> rows 2akp, 2akp+1
    const int amc = (t >> 4) << 3;     // A trans: m start (8 floats)
    const float* Aptr = TRANSA
        ? A + (size_t)(2 * akp) * lda + m0 + amc
        : A + (size_t)(m0 + am) * lda + akc;

    // ---- compute index maps (per warp: 64x64 tile) ----
    const int mw = (wid >> 2) << 6;    // 0 or 64
    const int nw = (wid & 3) << 6;     // 0,64,128,192
    const uint32_t a_off = (uint32_t)(mw + (lane & 15)) * 80u + ((lane >> 4) << 4);
    const int bkl = lane & 15;
    const int bnl = (lane >> 4) << 3;
    uint32_t b_off[4];
#pragma unroll
    for (int njp = 0; njp < 4; njp++)
        b_off[njp] = (uint32_t)bkl * 512u +
                     ((uint32_t)((nw + njp * 16 + bnl) << 1) ^ (uint32_t)((bkl & 7) << 4));

    float acc[4][8][4];
#pragma unroll
    for (int i = 0; i < 4; i++)
#pragma unroll
        for (int j = 0; j < 8; j++)
#pragma unroll
            for (int r = 0; r < 4; r++) acc[i][j][r] = 0.0f;

    float4 pa[4], pb[8];

    // ---- prologue: load tile 0 ----
#pragma unroll
    for (int q = 0; q < 8; q++) pb[q] = *(const float4*)(Bptr + q * 4);
    if (TRANSA) {
        pa[0] = *(const float4*)(Aptr);       pa[1] = *(const float4*)(Aptr + 4);
        pa[2] = *(const float4*)(Aptr + lda); pa[3] = *(const float4*)(Aptr + lda + 4);
    } else {
#pragma unroll
        for (int q = 0; q < 4; q++) pa[q] = *(const float4*)(Aptr + q * 4);
    }

    for (int kt = 0; kt < ktiles; kt++) {
        // ---- store prefetched regs -> stage kt&1 ----
        {
            char* sb = smem + (kt & 1) * STG;
            // B: 32 floats -> 4 hi uint4 + 4 lo uint4
#pragma unroll
            for (int j = 0; j < 4; j++) {
                uint4 H, L;
                split2(pb[2 * j].x, pb[2 * j].y, H.x, L.x);
                split2(pb[2 * j].z, pb[2 * j].w, H.y, L.y);
                split2(pb[2 * j + 1].x, pb[2 * j + 1].y, H.z, L.z);
                split2(pb[2 * j + 1].z, pb[2 * j + 1].w, H.w, L.w);
                uint32_t off = (uint32_t)bk * 512u +
                               (((uint32_t)((bn + j * 8) << 1)) ^ (uint32_t)((bk & 7) << 4));
                *(uint4*)(sb + BHI + off) = H;
                *(uint4*)(sb + BLO + off) = L;
            }
            // A tiles
            if (TRANSA) {
                float v0[8] = {pa[0].x, pa[0].y, pa[0].z, pa[0].w, pa[1].x, pa[1].y, pa[1].z, pa[1].w};
                float v1[8] = {pa[2].x, pa[2].y, pa[2].z, pa[2].w, pa[3].x, pa[3].y, pa[3].z, pa[3].w};
#pragma unroll
                for (int i = 0; i < 8; i++) {
                    uint32_t h, l;
                    split2(v0[i], v1[i], h, l);   // (k, k+1) pair at m = amc+i
                    uint32_t off = (uint32_t)(amc + i) * 80u + (uint32_t)(akp << 2);
                    *(uint32_t*)(sb + AHI + off) = h;
                    *(uint32_t*)(sb + ALO + off) = l;
                }
            } else {
#pragma unroll
                for (int j = 0; j < 2; j++) {
                    uint4 H, L;
                    split2(pa[2 * j].x, pa[2 * j].y, H.x, L.x);
                    split2(pa[2 * j].z, pa[2 * j].w, H.y, L.y);
                    split2(pa[2 * j + 1].x, pa[2 * j + 1].y, H.z, L.z);
                    split2(pa[2 * j + 1].z, pa[2 * j + 1].w, H.w, L.w);
                    uint32_t off = (uint32_t)am * 80u + (uint32_t)(akc << 1) + (uint32_t)(j << 4);
                    *(uint4*)(sb + AHI + off) = H;
                    *(uint4*)(sb + ALO + off) = L;
                }
            }
        }
        __syncthreads();

        // ---- prefetch next tile ----
        if (kt + 1 < ktiles) {
            const float* Bp = Bptr + (size_t)(kt + 1) * 32 * ldb;
#pragma unroll
            for (int q = 0; q < 8; q++) pb[q] = *(const float4*)(Bp + q * 4);
            if (TRANSA) {
                const float* Ap = Aptr + (size_t)(kt + 1) * 32 * lda;
                pa[0] = *(const float4*)(Ap);       pa[1] = *(const float4*)(Ap + 4);
                pa[2] = *(const float4*)(Ap + lda); pa[3] = *(const float4*)(Ap + lda + 4);
            } else {
                const float* Ap = Aptr + (size_t)(kt + 1) * 32;
#pragma unroll
                for (int q = 0; q < 4; q++) pa[q] = *(const float4*)(Ap + q * 4);
            }
        }

        // ---- compute on stage kt&1 ----
        {
            const uint32_t sb32 = sbase + (uint32_t)((kt & 1) * STG);
            const uint32_t ah = sb32 + AHI, al = sb32 + ALO;
            const uint32_t bh = sb32 + BHI, bl = sb32 + BLO;
#pragma unroll
            for (int ks = 0; ks < 2; ks++) {
                uint32_t Ah[4][4], Al[4][4];
#pragma unroll
                for (int mi = 0; mi < 4; mi++) {
                    const uint32_t ao = a_off + (uint32_t)(mi * 16 * 80) + (uint32_t)(ks * 32);
                    ldsm4(Ah[mi], ah + ao);
                    ldsm4(Al[mi], al + ao);
                }
#pragma unroll
                for (int njp = 0; njp < 4; njp++) {
                    uint32_t Bh[4], Bl[4];
                    const uint32_t bo = b_off[njp] + (uint32_t)(ks * 16 * 512);
                    ldsm4t(Bh, bh + bo);
                    ldsm4t(Bl, bl + bo);
#pragma unroll
                    for (int mi = 0; mi < 4; mi++)
#pragma unroll
                        for (int j = 0; j < 2; j++) {
                            float* d = acc[mi][njp * 2 + j];
                            mma16816(d, Ah[mi], &Bh[2 * j]);  // hi*hi
                            mma16816(d, Ah[mi], &Bl[2 * j]);  // hi*lo
                            mma16816(d, Al[mi], &Bh[2 * j]);  // lo*hi
                        }
                }
            }
        }
        __syncthreads();
    }

    // ---- epilogue: accumulators -> C (fp32) ----
    const int cm = m0 + mw + (lane >> 2);
    const int cn = n0 + nw + ((lane & 3) << 1);
#pragma unroll
    for (int mi = 0; mi < 4; mi++) {
#pragma unroll
        for (int nj = 0; nj < 8; nj++) {
            float* d = acc[mi][nj];
            float* c0 = C + (size_t)(cm + mi * 16) * ldc + cn + nj * 8;
            float* c1 = c0 + (size_t)8 * ldc;
            c0[0] = d[0]; c0[1] = d[1];
            c1[0] = d[2]; c1[1] = d[3];
        }
    }
}

// ---------------------------------------------------------------------------
// Row softmax over last dim (512), one block (128 thr) per row
// ---------------------------------------------------------------------------
__global__ void softmax_rows(float* __restrict__ att)
{
    __shared__ float smax[4];
    __shared__ float ssum[4];
    const int row = blockIdx.x;
    float4* p = (float4*)(att + (size_t)row * DD);
    const int t = threadIdx.x;

    float4 v = p[t];
    float m = fmaxf(fmaxf(v.x, v.y), fmaxf(v.z, v.w));
#pragma unroll
    for (int o = 16; o > 0; o >>= 1) m = fmaxf(m, __shfl_xor_sync(0xffffffffu, m, o));
    if ((t & 31) == 0) smax[t >> 5] = m;
    __syncthreads();
    m = fmaxf(fmaxf(smax[0], smax[1]), fmaxf(smax[2], smax[3]));

    v.x = expf(v.x - m); v.y = expf(v.y - m);
    v.z = expf(v.z - m); v.w = expf(v.w - m);
    float s = v.x + v.y + v.z + v.w;
#pragma unroll
    for (int o = 16; o > 0; o >>= 1) s += __shfl_xor_sync(0xffffffffu, s, o);
    if ((t & 31) == 0) ssum[t >> 5] = s;
    __syncthreads();
    s = ssum[0] + ssum[1] + ssum[2] + ssum[3];

    const float inv = 1.0f / s;
    v.x *= inv; v.y *= inv; v.z *= inv; v.w *= inv;
    p[t] = v;
}

extern "C" void kernel_launch(void* const* d_in, const int* in_sizes, int n_in,
                              void* d_out, int out_size)
{
    (void)in_sizes; (void)n_in; (void)out_size;
    const float* x  = (const float*)d_in[0];
    const float* w1 = (const float*)d_in[1];
    const float* w2 = (const float*)d_in[2];
    const float* w3 = (const float*)d_in[3];
    float* out = (float*)d_out;

    float *q, *k, *v, *att;
    cudaGetSymbolAddress((void**)&q,   g_q);
    cudaGetSymbolAddress((void**)&k,   g_k);
    cudaGetSymbolAddress((void**)&v,   g_v);
    cudaGetSymbolAddress((void**)&att, g_att);

    cudaFuncSetAttribute(hmma_gemm<false>, cudaFuncAttributeMaxDynamicSharedMemorySize, SMEM_REQ);
    cudaFuncSetAttribute(hmma_gemm<true>,  cudaFuncAttributeMaxDynamicSharedMemorySize, SMEM_REQ);

    const long strND = (long)DN * DD;
    const long strDD = (long)DD * DD;

    dim3 blk(256);
    dim3 gProj(16, NBE);   // (1024/128)*(512/256)
    dim3 gAtt(8, NBE);     // (512/128)*(512/256)

    // q/k/v = x @ w{1,2,3}   (M=1024, N=512, K=512)
    hmma_gemm<false><<<gProj, blk, SMEM_REQ>>>(x, w1, q, DD, DD, DD, strND, strDD, strND, DE, 16, 2);
    hmma_gemm<false><<<gProj, blk, SMEM_REQ>>>(x, w2, k, DD, DD, DD, strND, strDD, strND, DE, 16, 2);
    hmma_gemm<false><<<gProj, blk, SMEM_REQ>>>(x, w3, v, DD, DD, DD, strND, strDD, strND, DE, 16, 2);

    // att = q^T @ k          (M=512, N=512, K=1024)
    hmma_gemm<true><<<gAtt, blk, SMEM_REQ>>>(q, k, att, DD, DD, DD, strND, strND, strDD, NBE, 32, 2);

    // softmax over last dim
    softmax_rows<<<NBE * DD, 128>>>(att);

    // out = v @ att          (M=1024, N=512, K=512)
    hmma_gemm<false><<<gProj, blk, SMEM_REQ>>>(v, att, out, DD, DD, DD, strND, strDD, strND, NBE, 16, 2);
}

// round 10
// speedup vs baseline: 1.2507x; 1.2507x over previous
#include <cuda_runtime.h>
#include <cuda_bf16.h>
#include <cstdint>
#include <cstddef>

#define DB 4
#define DE 16
#define DN 1024
#define DD 512
#define NBE (DB * DE)

typedef __nv_bfloat16 bf16;

// ---------------- scratch (__device__ globals; no allocs allowed) ----------
__device__ __align__(256) bf16 g_xh[(size_t)DB * DE * DN * DD];
__device__ __align__(256) bf16 g_xl[(size_t)DB * DE * DN * DD];
__device__ __align__(256) bf16 g_wh[3][(size_t)DE * DD * DD];
__device__ __align__(256) bf16 g_wl[3][(size_t)DE * DD * DD];
__device__ __align__(256) bf16 g_qh[(size_t)NBE * DN * DD];
__device__ __align__(256) bf16 g_ql[(size_t)NBE * DN * DD];
__device__ __align__(256) bf16 g_kh[(size_t)NBE * DN * DD];
__device__ __align__(256) bf16 g_kl[(size_t)NBE * DN * DD];
__device__ __align__(256) bf16 g_vh[(size_t)NBE * DN * DD];
__device__ __align__(256) bf16 g_vl[(size_t)NBE * DN * DD];
__device__ __align__(256) float g_att[(size_t)NBE * DD * DD];
__device__ __align__(256) bf16 g_ah[(size_t)NBE * DD * DD];
__device__ __align__(256) bf16 g_al[(size_t)NBE * DD * DD];

// ---------------- helpers ----------------
__device__ __forceinline__ uint32_t smem_u32(const void* p) {
    uint32_t a;
    asm("{ .reg .u64 t; cvta.to.shared.u64 t, %1; cvt.u32.u64 %0, t; }" : "=r"(a) : "l"(p));
    return a;
}
__device__ __forceinline__ void ldsm4(uint32_t* r, uint32_t addr) {
    asm volatile("ldmatrix.sync.aligned.m8n8.x4.shared.b16 {%0,%1,%2,%3}, [%4];"
                 : "=r"(r[0]), "=r"(r[1]), "=r"(r[2]), "=r"(r[3]) : "r"(addr));
}
__device__ __forceinline__ void ldsm4t(uint32_t* r, uint32_t addr) {
    asm volatile("ldmatrix.sync.aligned.m8n8.x4.trans.shared.b16 {%0,%1,%2,%3}, [%4];"
                 : "=r"(r[0]), "=r"(r[1]), "=r"(r[2]), "=r"(r[3]) : "r"(addr));
}
__device__ __forceinline__ void mma16816(float* d, const uint32_t* a, const uint32_t* b) {
    asm volatile(
        "mma.sync.aligned.m16n8k16.row.col.f32.bf16.bf16.f32 "
        "{%0,%1,%2,%3}, {%4,%5,%6,%7}, {%8,%9}, {%0,%1,%2,%3};"
        : "+f"(d[0]), "+f"(d[1]), "+f"(d[2]), "+f"(d[3])
        : "r"(a[0]), "r"(a[1]), "r"(a[2]), "r"(a[3]), "r"(b[0]), "r"(b[1]));
}
__device__ __forceinline__ void split2(float x, float y, uint32_t& h, uint32_t& l) {
    __nv_bfloat162 hb = __floats2bfloat162_rn(x, y);
    float2 hf = __bfloat1622float2(hb);
    __nv_bfloat162 lb = __floats2bfloat162_rn(x - hf.x, y - hf.y);
    h = reinterpret_cast<uint32_t&>(hb);
    l = reinterpret_cast<uint32_t&>(lb);
}
__device__ __forceinline__ void cpa16(uint32_t dst, const void* src) {
    asm volatile("cp.async.cg.shared.global [%0], [%1], 16;" :: "r"(dst), "l"(src));
}
__device__ __forceinline__ void cpa_commit() {
    asm volatile("cp.async.commit_group;" ::: "memory");
}
template <int N>
__device__ __forceinline__ void cpa_wait() {
    asm volatile("cp.async.wait_group %0;" :: "n"(N) : "memory");
}

// ---------------------------------------------------------------------------
// HMMA bf16-split GEMM, pre-split operands.
// CTA tile 128(M) x 256(N), BK=32, 256 thr, 8 warps (2M x 4N) of 64x64.
// TRANSA=false: A hi/lo row-major M x K (lda) ; SMEM stride-80 layout, ldsm
// TRANSA=true : A hi/lo row-major K x M (lda) ; SMEM K-major 256B rows, ldsm.trans
// B hi/lo row-major K x N (ldb), SMEM 512B rows xor-swizzle, ldsm.trans.
// C: fp32 (Cf) or split hi/lo (Chi/Clo) per OUT_SPLIT.
// ---------------------------------------------------------------------------
template <bool TRANSA, bool OUT_SPLIT>
__global__ __launch_bounds__(256, 1) void hmma_gemm(
    const bf16* __restrict__ Ahg, const bf16* __restrict__ Alg,
    const bf16* __restrict__ Bhg, const bf16* __restrict__ Blg,
    float* __restrict__ Cf, bf16* __restrict__ Chi, bf16* __restrict__ Clo,
    int lda, int ldb, int ldc, long sA, long sB, long sC, int modB, int ktiles, int ntile)
{
    constexpr int AH  = 0;
    constexpr int AL  = TRANSA ? 8192 : 10240;
    constexpr int BH  = 2 * AL;
    constexpr int BL  = BH + 16384;
    constexpr int STG = BL + 16384;

    extern __shared__ __align__(1024) char smem[];
    const uint32_t sbase = smem_u32(smem);

    const int t    = threadIdx.x;
    const int lane = t & 31;
    const int wid  = t >> 5;
    const int be   = blockIdx.y;
    const bf16* Ah = Ahg + (size_t)be * sA;
    const bf16* Al = Alg + (size_t)be * sA;
    const bf16* Bh = Bhg + (size_t)(be % modB) * sB;
    const bf16* Bl = Blg + (size_t)(be % modB) * sB;

    const int m0 = (blockIdx.x / ntile) << 7;
    const int n0 = (blockIdx.x % ntile) << 8;

    // ---- loader maps (cp.async, 16B chunks) ----
    // B: k = t>>3 (0..31), chunks (t&7)*4 .. +3 of 32 (512B row)
    const int lbk = t >> 3;
    const int lbc = (t & 7) << 2;
    const uint32_t bsw = (uint32_t)((lbk & 7) << 4);
    const bf16* BhR = Bh + (size_t)lbk * ldb + n0 + lbc * 8;
    const bf16* BlR = Bl + (size_t)lbk * ldb + n0 + lbc * 8;
    const uint32_t bdst = (uint32_t)lbk * 512u;
    // A maps
    const int lak = t >> 3;            // TRANSA: k row
    const int lac = (t & 7) << 1;      // TRANSA: chunks (2) of 16 (256B row)
    const int lam = t >> 1;            // !TRANSA: m row
    const int lkc = (t & 1) << 1;      // !TRANSA: chunks (2) of 4 (64B data)
    const bf16* AhR;
    const bf16* AlR;
    uint32_t adst0, adst1;
    if (TRANSA) {
        AhR = Ah + (size_t)lak * lda + m0 + lac * 8;
        AlR = Al + (size_t)lak * lda + m0 + lac * 8;
        const uint32_t asw = (uint32_t)((lak & 7) << 4);
        adst0 = (uint32_t)lak * 256u + (((uint32_t)(lac * 16)) ^ asw);
        adst1 = (uint32_t)lak * 256u + (((uint32_t)((lac + 1) * 16)) ^ asw);
    } else {
        AhR = Ah + (size_t)(m0 + lam) * lda + lkc * 8;
        AlR = Al + (size_t)(m0 + lam) * lda + lkc * 8;
        adst0 = (uint32_t)lam * 80u + (uint32_t)(lkc * 16);
        adst1 = adst0 + 16u;
    }
    const int astep = TRANSA ? 32 * lda : 32;   // elements per kt for A src
    const int bstep = 32 * ldb;

    // ---- compute maps (warp 64x64) ----
    const int mw = (wid >> 2) << 6;
    const int nw = (wid & 3) << 6;
    // A (!TRANSA): stride-80 rows
    const uint32_t a_off = (uint32_t)(mw + (lane & 15)) * 80u + ((lane >> 4) << 4);
    // A (TRANSA): K-major, ldsm.trans ; kl = k-lane, mbit = +8 col group
    const int kl = (lane & 7) | ((lane >> 4) << 3);
    const int mbit = (lane >> 3) & 1;
    const uint32_t atsw = (uint32_t)((kl & 7) << 4);
    // B: ldsm.trans
    const int bkl = lane & 15;
    const int bnl = (lane >> 4) << 3;
    uint32_t b_off[4];
#pragma unroll
    for (int njp = 0; njp < 4; njp++)
        b_off[njp] = (uint32_t)bkl * 512u +
                     ((uint32_t)((nw + njp * 16 + bnl) << 1) ^ (uint32_t)((bkl & 7) << 4));

    float acc[4][8][4];
#pragma unroll
    for (int i = 0; i < 4; i++)
#pragma unroll
        for (int j = 0; j < 8; j++)
#pragma unroll
            for (int r = 0; r < 4; r++) acc[i][j][r] = 0.0f;

    // ---- cp.async stage issue ----
    auto issue = [&](int s, int kt) {
        const uint32_t sb = sbase + (uint32_t)(s * STG);
        const bf16* bh = BhR + (size_t)kt * bstep;
        const bf16* bl = BlR + (size_t)kt * bstep;
#pragma unroll
        for (int c = 0; c < 4; c++) {
            const uint32_t d = sb + BH + bdst + (((uint32_t)((lbc + c) * 16)) ^ bsw);
            cpa16(d, bh + c * 8);
            cpa16(d + (BL - BH), bl + c * 8);
        }
        const bf16* ah = AhR + (size_t)kt * astep;
        const bf16* al = AlR + (size_t)kt * astep;
        cpa16(sb + AH + adst0, ah);
        cpa16(sb + AH + adst1, ah + 8);
        cpa16(sb + AL + adst0, al);
        cpa16(sb + AL + adst1, al + 8);
    };

    issue(0, 0); cpa_commit();
    issue(1, 1); cpa_commit();

    int s = 0;
    for (int kt = 0; kt < ktiles; kt++) {
        if (kt + 2 < ktiles) {
            int s2 = s + 2; if (s2 >= 3) s2 -= 3;
            issue(s2, kt + 2); cpa_commit();
            cpa_wait<2>();
        } else if (kt + 2 == ktiles) {
            cpa_wait<1>();
        } else {
            cpa_wait<0>();
        }
        __syncthreads();

        const uint32_t sb32 = sbase + (uint32_t)(s * STG);
        const uint32_t ah = sb32 + AH, al = sb32 + AL;
        const uint32_t bh = sb32 + BH, bl = sb32 + BL;
#pragma unroll
        for (int ks = 0; ks < 2; ks++) {
            uint32_t Afh[4][4], Afl[4][4];
#pragma unroll
            for (int mi = 0; mi < 4; mi++) {
                if (TRANSA) {
                    const uint32_t mcol2 = (uint32_t)((mw + mi * 16 + mbit * 8) << 1);
                    const uint32_t ao = (uint32_t)((ks * 16 + kl) * 256) + (mcol2 ^ atsw);
                    ldsm4t(Afh[mi], ah + ao);
                    ldsm4t(Afl[mi], al + ao);
                } else {
                    const uint32_t ao = a_off + (uint32_t)(mi * 16 * 80) + (uint32_t)(ks * 32);
                    ldsm4(Afh[mi], ah + ao);
                    ldsm4(Afl[mi], al + ao);
                }
            }
#pragma unroll
            for (int njp = 0; njp < 4; njp++) {
                uint32_t Bfh[4], Bfl[4];
                const uint32_t bo = b_off[njp] + (uint32_t)(ks * 16 * 512);
                ldsm4t(Bfh, bh + bo);
                ldsm4t(Bfl, bl + bo);
#pragma unroll
                for (int mi = 0; mi < 4; mi++)
#pragma unroll
                    for (int j = 0; j < 2; j++) {
                        float* d = acc[mi][njp * 2 + j];
                        mma16816(d, Afh[mi], &Bfh[2 * j]);  // hi*hi
                        mma16816(d, Afh[mi], &Bfl[2 * j]);  // hi*lo
                        mma16816(d, Afl[mi], &Bfh[2 * j]);  // lo*hi
                    }
            }
        }
        __syncthreads();
        if (++s == 3) s = 0;
    }

    // ---- epilogue ----
    const int cm = m0 + mw + (lane >> 2);
    const int cn = n0 + nw + ((lane & 3) << 1);
#pragma unroll
    for (int mi = 0; mi < 4; mi++) {
#pragma unroll
        for (int nj = 0; nj < 8; nj++) {
            float* d = acc[mi][nj];
            const size_t i0 = (size_t)(cm + mi * 16) * ldc + cn + nj * 8 + (size_t)be * sC;
            const size_t i1 = i0 + (size_t)8 * ldc;
            if (OUT_SPLIT) {
                uint32_t h0, l0, h1, l1;
                split2(d[0], d[1], h0, l0);
                split2(d[2], d[3], h1, l1);
                *(uint32_t*)(Chi + i0) = h0;
                *(uint32_t*)(Clo + i0) = l0;
                *(uint32_t*)(Chi + i1) = h1;
                *(uint32_t*)(Clo + i1) = l1;
            } else {
                Cf[i0] = d[0]; Cf[i0 + 1] = d[1];
                Cf[i1] = d[2]; Cf[i1 + 1] = d[3];
            }
        }
    }
}

// ---------------------------------------------------------------------------
// fp32 -> bf16 hi/lo elementwise split (x, w pre-conversion)
// ---------------------------------------------------------------------------
__global__ void split_conv(const float4* __restrict__ in,
                           uint32_t* __restrict__ hi, uint32_t* __restrict__ lo, int n4)
{
    const int i = blockIdx.x * blockDim.x + threadIdx.x;
    if (i >= n4) return;
    float4 v = in[i];
    uint32_t h0, l0, h1, l1;
    split2(v.x, v.y, h0, l0);
    split2(v.z, v.w, h1, l1);
    hi[2 * i] = h0; hi[2 * i + 1] = h1;
    lo[2 * i] = l0; lo[2 * i + 1] = l1;
}

// ---------------------------------------------------------------------------
// Row softmax over last dim (512) -> writes bf16 hi/lo
// ---------------------------------------------------------------------------
__global__ void softmax_rows(const float* __restrict__ att,
                             uint32_t* __restrict__ ah, uint32_t* __restrict__ al)
{
    __shared__ float smax[4];
    __shared__ float ssum[4];
    const int row = blockIdx.x;
    const float4* p = (const float4*)(att + (size_t)row * DD);
    const int t = threadIdx.x;

    float4 v = p[t];
    float m = fmaxf(fmaxf(v.x, v.y), fmaxf(v.z, v.w));
#pragma unroll
    for (int o = 16; o > 0; o >>= 1) m = fmaxf(m, __shfl_xor_sync(0xffffffffu, m, o));
    if ((t & 31) == 0) smax[t >> 5] = m;
    __syncthreads();
    m = fmaxf(fmaxf(smax[0], smax[1]), fmaxf(smax[2], smax[3]));

    v.x = expf(v.x - m); v.y = expf(v.y - m);
    v.z = expf(v.z - m); v.w = expf(v.w - m);
    float s = v.x + v.y + v.z + v.w;
#pragma unroll
    for (int o = 16; o > 0; o >>= 1) s += __shfl_xor_sync(0xffffffffu, s, o);
    if ((t & 31) == 0) ssum[t >> 5] = s;
    __syncthreads();
    s = ssum[0] + ssum[1] + ssum[2] + ssum[3];

    const float inv = 1.0f / s;
    uint32_t h0, l0, h1, l1;
    split2(v.x * inv, v.y * inv, h0, l0);
    split2(v.z * inv, v.w * inv, h1, l1);
    const size_t o2 = (size_t)row * (DD / 2) + 2 * t;
    ah[o2] = h0; ah[o2 + 1] = h1;
    al[o2] = l0; al[o2 + 1] = l1;
}

extern "C" void kernel_launch(void* const* d_in, const int* in_sizes, int n_in,
                              void* d_out, int out_size)
{
    (void)in_sizes; (void)n_in; (void)out_size;
    const float* x  = (const float*)d_in[0];
    const float* w1 = (const float*)d_in[1];
    const float* w2 = (const float*)d_in[2];
    const float* w3 = (const float*)d_in[3];
    float* out = (float*)d_out;

    bf16 *xh, *xl, *wh0, *wl0, *qh, *ql, *kh, *kl_, *vh, *vl, *ath, *atl;
    float* att;
    cudaGetSymbolAddress((void**)&xh, g_xh);
    cudaGetSymbolAddress((void**)&xl, g_xl);
    cudaGetSymbolAddress((void**)&wh0, g_wh);
    cudaGetSymbolAddress((void**)&wl0, g_wl);
    cudaGetSymbolAddress((void**)&qh, g_qh);
    cudaGetSymbolAddress((void**)&ql, g_ql);
    cudaGetSymbolAddress((void**)&kh, g_kh);
    cudaGetSymbolAddress((void**)&kl_, g_kl);
    cudaGetSymbolAddress((void**)&vh, g_vh);
    cudaGetSymbolAddress((void**)&vl, g_vl);
    cudaGetSymbolAddress((void**)&att, g_att);
    cudaGetSymbolAddress((void**)&ath, g_ah);
    cudaGetSymbolAddress((void**)&atl, g_al);

    const size_t WSZ = (size_t)DE * DD * DD;
    bf16* wh[3] = {wh0, wh0 + WSZ, wh0 + 2 * WSZ};
    bf16* wl[3] = {wl0, wl0 + WSZ, wl0 + 2 * WSZ};

    static bool init_done = false;
    if (!init_done) {
        cudaFuncSetAttribute(hmma_gemm<false, true>,  cudaFuncAttributeMaxDynamicSharedMemorySize, 3 * 53248);
        cudaFuncSetAttribute(hmma_gemm<false, false>, cudaFuncAttributeMaxDynamicSharedMemorySize, 3 * 53248);
        cudaFuncSetAttribute(hmma_gemm<true, false>,  cudaFuncAttributeMaxDynamicSharedMemorySize, 3 * 49152);
        init_done = true;
    }

    // ---- pre-split x and weights ----
    {
        const int n4x = (DB * DE * DN * DD) / 4;
        split_conv<<<(n4x + 255) / 256, 256>>>((const float4*)x, (uint32_t*)xh, (uint32_t*)xl, n4x);
        const int n4w = (DE * DD * DD) / 4;
        split_conv<<<(n4w + 255) / 256, 256>>>((const float4*)w1, (uint32_t*)wh[0], (uint32_t*)wl[0], n4w);
        split_conv<<<(n4w + 255) / 256, 256>>>((const float4*)w2, (uint32_t*)wh[1], (uint32_t*)wl[1], n4w);
        split_conv<<<(n4w + 255) / 256, 256>>>((const float4*)w3, (uint32_t*)wh[2], (uint32_t*)wl[2], n4w);
    }

    const long strND = (long)DN * DD;
    const long strDD = (long)DD * DD;

    dim3 blk(256);
    dim3 gProj(16, NBE);   // (1024/128)*(512/256)
    dim3 gAtt(8, NBE);     // (512/128)*(512/256)

    // q/k/v = x @ w  (M=1024, N=512, K=512) -> split bf16 outputs
    hmma_gemm<false, true><<<gProj, blk, 3 * 53248>>>(
        xh, xl, wh[0], wl[0], nullptr, qh, ql, DD, DD, DD, strND, strDD, strND, DE, 16, 2);
    hmma_gemm<false, true><<<gProj, blk, 3 * 53248>>>(
        xh, xl, wh[1], wl[1], nullptr, kh, kl_, DD, DD, DD, strND, strDD, strND, DE, 16, 2);
    hmma_gemm<false, true><<<gProj, blk, 3 * 53248>>>(
        xh, xl, wh[2], wl[2], nullptr, vh, vl, DD, DD, DD, strND, strDD, strND, DE, 16, 2);

    // att = q^T @ k  (M=512, N=512, K=1024) -> fp32
    hmma_gemm<true, false><<<gAtt, blk, 3 * 49152>>>(
        qh, ql, kh, kl_, att, nullptr, nullptr, DD, DD, DD, strND, strND, strDD, NBE, 32, 2);

    // softmax -> split bf16
    softmax_rows<<<NBE * DD, 128>>>(att, (uint32_t*)ath, (uint32_t*)atl);

    // out = v @ att  (M=1024, N=512, K=512) -> fp32
    hmma_gemm<false, false><<<gProj, blk, 3 * 53248>>>(
        vh, vl, ath, atl, out, nullptr, nullptr, DD, DD, DD, strND, strDD, strND, NBE, 16, 2);
}

// round 13
// speedup vs baseline: 1.5100x; 1.2073x over previous
#include <cuda_runtime.h>
#include <cuda_bf16.h>
#include <cstdint>
#include <cstddef>

#define DB 4
#define DE 16
#define DN 1024
#define DD 512
#define NBE (DB * DE)

typedef __nv_bfloat16 bf16;

// ---------------- scratch (__device__ globals; no allocs allowed) ----------
__device__ __align__(256) bf16 g_xh[(size_t)DB * DE * DN * DD];
__device__ __align__(256) bf16 g_xl[(size_t)DB * DE * DN * DD];
__device__ __align__(256) bf16 g_wh[3][(size_t)DE * DD * DD];
__device__ __align__(256) bf16 g_wl[3][(size_t)DE * DD * DD];
__device__ __align__(256) bf16 g_Gh[(size_t)NBE * DD * DD];
__device__ __align__(256) bf16 g_Gl[(size_t)NBE * DD * DD];
__device__ __align__(256) bf16 g_Th[(size_t)NBE * DD * DD];
__device__ __align__(256) bf16 g_Tl[(size_t)NBE * DD * DD];
__device__ __align__(256) bf16 g_vh[(size_t)NBE * DN * DD];
__device__ __align__(256) bf16 g_vl[(size_t)NBE * DN * DD];
__device__ __align__(256) float g_att[(size_t)NBE * DD * DD];
__device__ __align__(256) bf16 g_ah[(size_t)NBE * DD * DD];
__device__ __align__(256) bf16 g_al[(size_t)NBE * DD * DD];

// ---------------- helpers ----------------
__device__ __forceinline__ uint32_t smem_u32(const void* p) {
    uint32_t a;
    asm("{ .reg .u64 t; cvta.to.shared.u64 t, %1; cvt.u32.u64 %0, t; }" : "=r"(a) : "l"(p));
    return a;
}
__device__ __forceinline__ void ldsm4(uint32_t* r, uint32_t addr) {
    asm volatile("ldmatrix.sync.aligned.m8n8.x4.shared.b16 {%0,%1,%2,%3}, [%4];"
                 : "=r"(r[0]), "=r"(r[1]), "=r"(r[2]), "=r"(r[3]) : "r"(addr));
}
__device__ __forceinline__ void ldsm4t(uint32_t* r, uint32_t addr) {
    asm volatile("ldmatrix.sync.aligned.m8n8.x4.trans.shared.b16 {%0,%1,%2,%3}, [%4];"
                 : "=r"(r[0]), "=r"(r[1]), "=r"(r[2]), "=r"(r[3]) : "r"(addr));
}
__device__ __forceinline__ void mma16816(float* d, const uint32_t* a, const uint32_t* b) {
    asm volatile(
        "mma.sync.aligned.m16n8k16.row.col.f32.bf16.bf16.f32 "
        "{%0,%1,%2,%3}, {%4,%5,%6,%7}, {%8,%9}, {%0,%1,%2,%3};"
        : "+f"(d[0]), "+f"(d[1]), "+f"(d[2]), "+f"(d[3])
        : "r"(a[0]), "r"(a[1]), "r"(a[2]), "r"(a[3]), "r"(b[0]), "r"(b[1]));
}
__device__ __forceinline__ void split2(float x, float y, uint32_t& h, uint32_t& l) {
    __nv_bfloat162 hb = __floats2bfloat162_rn(x, y);
    float2 hf = __bfloat1622float2(hb);
    __nv_bfloat162 lb = __floats2bfloat162_rn(x - hf.x, y - hf.y);
    h = reinterpret_cast<uint32_t&>(hb);
    l = reinterpret_cast<uint32_t&>(lb);
}
__device__ __forceinline__ void cpa16(uint32_t dst, const void* src) {
    asm volatile("cp.async.cg.shared.global [%0], [%1], 16;" :: "r"(dst), "l"(src));
}
__device__ __forceinline__ void cpa_commit() {
    asm volatile("cp.async.commit_group;" ::: "memory");
}
template <int N>
__device__ __forceinline__ void cpa_wait() {
    asm volatile("cp.async.wait_group %0;" :: "n"(N) : "memory");
}

// ---------------------------------------------------------------------------
// HMMA bf16-split GEMM, pre-split operands.
// CTA tile 128(M) x 256(N), BK=32, 256 thr, 8 warps (2M x 4N) of 64x64.
// TRANSA=false: A hi/lo row-major M x K (lda) ; SMEM stride-80 layout, ldsm
// TRANSA=true : A hi/lo row-major K x M (lda) ; SMEM K-major 256B rows, ldsm.trans
// B hi/lo row-major K x N (ldb), SMEM 512B rows xor-swizzle, ldsm.trans.
// C: fp32 (Cf) or split hi/lo (Chi/Clo) per OUT_SPLIT.
// Batch: A += (be%modA)*sA ; B += (be%modB)*sB ; C += be*sC
// ---------------------------------------------------------------------------
template <bool TRANSA, bool OUT_SPLIT>
__global__ __launch_bounds__(256, 1) void hmma_gemm(
    const bf16* __restrict__ Ahg, const bf16* __restrict__ Alg,
    const bf16* __restrict__ Bhg, const bf16* __restrict__ Blg,
    float* __restrict__ Cf, bf16* __restrict__ Chi, bf16* __restrict__ Clo,
    int lda, int ldb, int ldc, long sA, long sB, long sC,
    int modA, int modB, int ktiles, int ntile)
{
    constexpr int AH  = 0;
    constexpr int AL  = TRANSA ? 8192 : 10240;
    constexpr int BH  = 2 * AL;
    constexpr int BL  = BH + 16384;
    constexpr int STG = BL + 16384;

    extern __shared__ __align__(1024) char smem[];
    const uint32_t sbase = smem_u32(smem);

    const int t    = threadIdx.x;
    const int lane = t & 31;
    const int wid  = t >> 5;
    const int be   = blockIdx.y;
    const bf16* Ah = Ahg + (size_t)(be % modA) * sA;
    const bf16* Al = Alg + (size_t)(be % modA) * sA;
    const bf16* Bh = Bhg + (size_t)(be % modB) * sB;
    const bf16* Bl = Blg + (size_t)(be % modB) * sB;

    const int m0 = (blockIdx.x / ntile) << 7;
    const int n0 = (blockIdx.x % ntile) << 8;

    // ---- loader maps (cp.async, 16B chunks) ----
    const int lbk = t >> 3;
    const int lbc = (t & 7) << 2;
    const uint32_t bsw = (uint32_t)((lbk & 7) << 4);
    const bf16* BhR = Bh + (size_t)lbk * ldb + n0 + lbc * 8;
    const bf16* BlR = Bl + (size_t)lbk * ldb + n0 + lbc * 8;
    const uint32_t bdst = (uint32_t)lbk * 512u;
    const int lak = t >> 3;            // TRANSA: k row
    const int lac = (t & 7) << 1;      // TRANSA: chunks (2) of 16 (256B row)
    const int lam = t >> 1;            // !TRANSA: m row
    const int lkc = (t & 1) << 1;      // !TRANSA: chunks (2)
    const bf16* AhR;
    const bf16* AlR;
    uint32_t adst0, adst1;
    if (TRANSA) {
        AhR = Ah + (size_t)lak * lda + m0 + lac * 8;
        AlR = Al + (size_t)lak * lda + m0 + lac * 8;
        const uint32_t asw = (uint32_t)((lak & 7) << 4);
        adst0 = (uint32_t)lak * 256u + (((uint32_t)(lac * 16)) ^ asw);
        adst1 = (uint32_t)lak * 256u + (((uint32_t)((lac + 1) * 16)) ^ asw);
    } else {
        AhR = Ah + (size_t)(m0 + lam) * lda + lkc * 8;
        AlR = Al + (size_t)(m0 + lam) * lda + lkc * 8;
        adst0 = (uint32_t)lam * 80u + (uint32_t)(lkc * 16);
        adst1 = adst0 + 16u;
    }
    const int astep = TRANSA ? 32 * lda : 32;
    const int bstep = 32 * ldb;

    // ---- compute maps (warp 64x64) ----
    const int mw = (wid >> 2) << 6;
    const int nw = (wid & 3) << 6;
    const uint32_t a_off = (uint32_t)(mw + (lane & 15)) * 80u + ((lane >> 4) << 4);
    const int kl = (lane & 7) | ((lane >> 4) << 3);
    const int mbit = (lane >> 3) & 1;
    const uint32_t atsw = (uint32_t)((kl & 7) << 4);
    const int bkl = lane & 15;
    const int bnl = (lane >> 4) << 3;
    uint32_t b_off[4];
#pragma unroll
    for (int njp = 0; njp < 4; njp++)
        b_off[njp] = (uint32_t)bkl * 512u +
                     ((uint32_t)((nw + njp * 16 + bnl) << 1) ^ (uint32_t)((bkl & 7) << 4));

    float acc[4][8][4];
#pragma unroll
    for (int i = 0; i < 4; i++)
#pragma unroll
        for (int j = 0; j < 8; j++)
#pragma unroll
            for (int r = 0; r < 4; r++) acc[i][j][r] = 0.0f;

    auto issue = [&](int s, int kt) {
        const uint32_t sb = sbase + (uint32_t)(s * STG);
        const bf16* bh = BhR + (size_t)kt * bstep;
        const bf16* bl = BlR + (size_t)kt * bstep;
#pragma unroll
        for (int c = 0; c < 4; c++) {
            const uint32_t d = sb + BH + bdst + (((uint32_t)((lbc + c) * 16)) ^ bsw);
            cpa16(d, bh + c * 8);
            cpa16(d + (BL - BH), bl + c * 8);
        }
        const bf16* ah = AhR + (size_t)kt * astep;
        const bf16* al = AlR + (size_t)kt * astep;
        cpa16(sb + AH + adst0, ah);
        cpa16(sb + AH + adst1, ah + 8);
        cpa16(sb + AL + adst0, al);
        cpa16(sb + AL + adst1, al + 8);
    };

    issue(0, 0); cpa_commit();
    issue(1, 1); cpa_commit();

    int s = 0;
    for (int kt = 0; kt < ktiles; kt++) {
        if (kt + 2 < ktiles) {
            int s2 = s + 2; if (s2 >= 3) s2 -= 3;
            issue(s2, kt + 2); cpa_commit();
            cpa_wait<2>();
        } else if (kt + 2 == ktiles) {
            cpa_wait<1>();
        } else {
            cpa_wait<0>();
        }
        __syncthreads();

        const uint32_t sb32 = sbase + (uint32_t)(s * STG);
        const uint32_t ah = sb32 + AH, al = sb32 + AL;
        const uint32_t bh = sb32 + BH, bl = sb32 + BL;
#pragma unroll
        for (int ks = 0; ks < 2; ks++) {
            uint32_t Afh[4][4], Afl[4][4];
#pragma unroll
            for (int mi = 0; mi < 4; mi++) {
                if (TRANSA) {
                    const uint32_t mcol2 = (uint32_t)((mw + mi * 16 + mbit * 8) << 1);
                    const uint32_t ao = (uint32_t)((ks * 16 + kl) * 256) + (mcol2 ^ atsw);
                    ldsm4t(Afh[mi], ah + ao);
                    ldsm4t(Afl[mi], al + ao);
                } else {
                    const uint32_t ao = a_off + (uint32_t)(mi * 16 * 80) + (uint32_t)(ks * 32);
                    ldsm4(Afh[mi], ah + ao);
                    ldsm4(Afl[mi], al + ao);
                }
            }
#pragma unroll
            for (int njp = 0; njp < 4; njp++) {
                uint32_t Bfh[4], Bfl[4];
                const uint32_t bo = b_off[njp] + (uint32_t)(ks * 16 * 512);
                ldsm4t(Bfh, bh + bo);
                ldsm4t(Bfl, bl + bo);
#pragma unroll
                for (int mi = 0; mi < 4; mi++)
#pragma unroll
                    for (int j = 0; j < 2; j++) {
                        float* d = acc[mi][njp * 2 + j];
                        mma16816(d, Afh[mi], &Bfh[2 * j]);  // hi*hi
                        mma16816(d, Afh[mi], &Bfl[2 * j]);  // hi*lo
                        mma16816(d, Afl[mi], &Bfh[2 * j]);  // lo*hi
                    }
            }
        }
        __syncthreads();
        if (++s == 3) s = 0;
    }

    // ---- epilogue ----
    const int cm = m0 + mw + (lane >> 2);
    const int cn = n0 + nw + ((lane & 3) << 1);
#pragma unroll
    for (int mi = 0; mi < 4; mi++) {
#pragma unroll
        for (int nj = 0; nj < 8; nj++) {
            float* d = acc[mi][nj];
            const size_t i0 = (size_t)(cm + mi * 16) * ldc + cn + nj * 8 + (size_t)be * sC;
            const size_t i1 = i0 + (size_t)8 * ldc;
            if (OUT_SPLIT) {
                uint32_t h0, l0, h1, l1;
                split2(d[0], d[1], h0, l0);
                split2(d[2], d[3], h1, l1);
                *(uint32_t*)(Chi + i0) = h0;
                *(uint32_t*)(Clo + i0) = l0;
                *(uint32_t*)(Chi + i1) = h1;
                *(uint32_t*)(Clo + i1) = l1;
            } else {
                Cf[i0] = d[0]; Cf[i0 + 1] = d[1];
                Cf[i1] = d[2]; Cf[i1 + 1] = d[3];
            }
        }
    }
}

// ---------------------------------------------------------------------------
// fp32 -> bf16 hi/lo elementwise split
// ---------------------------------------------------------------------------
__global__ void split_conv(const float4* __restrict__ in,
                           uint32_t* __restrict__ hi, uint32_t* __restrict__ lo, int n4)
{
    const int i = blockIdx.x * blockDim.x + threadIdx.x;
    if (i >= n4) return;
    float4 v = in[i];
    uint32_t h0, l0, h1, l1;
    split2(v.x, v.y, h0, l0);
    split2(v.z, v.w, h1, l1);
    hi[2 * i] = h0; hi[2 * i + 1] = h1;
    lo[2 * i] = l0; lo[2 * i + 1] = l1;
}

// ---------------------------------------------------------------------------
// Row softmax over last dim (512) -> writes bf16 hi/lo
// ---------------------------------------------------------------------------
__global__ void softmax_rows(const float* __restrict__ att,
                             uint32_t* __restrict__ ah, uint32_t* __restrict__ al)
{
    __shared__ float smax[4];
    __shared__ float ssum[4];
    const int row = blockIdx.x;
    const float4* p = (const float4*)(att + (size_t)row * DD);
    const int t = threadIdx.x;

    float4 v = p[t];
    float m = fmaxf(fmaxf(v.x, v.y), fmaxf(v.z, v.w));
#pragma unroll
    for (int o = 16; o > 0; o >>= 1) m = fmaxf(m, __shfl_xor_sync(0xffffffffu, m, o));
    if ((t & 31) == 0) smax[t >> 5] = m;
    __syncthreads();
    m = fmaxf(fmaxf(smax[0], smax[1]), fmaxf(smax[2], smax[3]));

    v.x = expf(v.x - m); v.y = expf(v.y - m);
    v.z = expf(v.z - m); v.w = expf(v.w - m);
    float s = v.x + v.y + v.z + v.w;
#pragma unroll
    for (int o = 16; o > 0; o >>= 1) s += __shfl_xor_sync(0xffffffffu, s, o);
    if ((t & 31) == 0) ssum[t >> 5] = s;
    __syncthreads();
    s = ssum[0] + ssum[1] + ssum[2] + ssum[3];

    const float inv = 1.0f / s;
    uint32_t h0, l0, h1, l1;
    split2(v.x * inv, v.y * inv, h0, l0);
    split2(v.z * inv, v.w * inv, h1, l1);
    const size_t o2 = (size_t)row * (DD / 2) + 2 * t;
    ah[o2] = h0; ah[o2 + 1] = h1;
    al[o2] = l0; al[o2 + 1] = l1;
}

extern "C" void kernel_launch(void* const* d_in, const int* in_sizes, int n_in,
                              void* d_out, int out_size)
{
    (void)in_sizes; (void)n_in; (void)out_size;
    const float* x  = (const float*)d_in[0];
    const float* w1 = (const float*)d_in[1];
    const float* w2 = (const float*)d_in[2];
    const float* w3 = (const float*)d_in[3];
    float* out = (float*)d_out;

    bf16 *xh, *xl, *wh0, *wl0, *Gh, *Gl, *Th, *Tl, *vh, *vl, *ath, *atl;
    float* att;
    cudaGetSymbolAddress((void**)&xh, g_xh);
    cudaGetSymbolAddress((void**)&xl, g_xl);
    cudaGetSymbolAddress((void**)&wh0, g_wh);
    cudaGetSymbolAddress((void**)&wl0, g_wl);
    cudaGetSymbolAddress((void**)&Gh, g_Gh);
    cudaGetSymbolAddress((void**)&Gl, g_Gl);
    cudaGetSymbolAddress((void**)&Th, g_Th);
    cudaGetSymbolAddress((void**)&Tl, g_Tl);
    cudaGetSymbolAddress((void**)&vh, g_vh);
    cudaGetSymbolAddress((void**)&vl, g_vl);
    cudaGetSymbolAddress((void**)&att, g_att);
    cudaGetSymbolAddress((void**)&ath, g_ah);
    cudaGetSymbolAddress((void**)&atl, g_al);

    const size_t WSZ = (size_t)DE * DD * DD;
    bf16* wh[3] = {wh0, wh0 + WSZ, wh0 + 2 * WSZ};
    bf16* wl[3] = {wl0, wl0 + WSZ, wl0 + 2 * WSZ};

    cudaFuncSetAttribute(hmma_gemm<false, true>,  cudaFuncAttributeMaxDynamicSharedMemorySize, 3 * 53248);
    cudaFuncSetAttribute(hmma_gemm<false, false>, cudaFuncAttributeMaxDynamicSharedMemorySize, 3 * 53248);
    cudaFuncSetAttribute(hmma_gemm<true, false>,  cudaFuncAttributeMaxDynamicSharedMemorySize, 3 * 49152);
    cudaFuncSetAttribute(hmma_gemm<true, true>,   cudaFuncAttributeMaxDynamicSharedMemorySize, 3 * 49152);

    // ---- pre-split x and weights ----
    {
        const int n4x = (DB * DE * DN * DD) / 4;
        split_conv<<<(n4x + 255) / 256, 256>>>((const float4*)x, (uint32_t*)xh, (uint32_t*)xl, n4x);
        const int n4w = (DE * DD * DD) / 4;
        split_conv<<<(n4w + 255) / 256, 256>>>((const float4*)w1, (uint32_t*)wh[0], (uint32_t*)wl[0], n4w);
        split_conv<<<(n4w + 255) / 256, 256>>>((const float4*)w2, (uint32_t*)wh[1], (uint32_t*)wl[1], n4w);
        split_conv<<<(n4w + 255) / 256, 256>>>((const float4*)w3, (uint32_t*)wh[2], (uint32_t*)wl[2], n4w);
    }

    const long strND = (long)DN * DD;
    const long strDD = (long)DD * DD;

    dim3 blk(256);
    dim3 gBig(16, NBE);    // M=1024: (1024/128)*(512/256)
    dim3 gSml(8,  NBE);    // M=512 : (512/128)*(512/256)

    // G = x^T x        (M=512, N=512, K=1024) -> split bf16
    hmma_gemm<true, true><<<gSml, blk, 3 * 49152>>>(
        xh, xl, xh, xl, nullptr, Gh, Gl, DD, DD, DD, strND, strND, strDD, NBE, NBE, 32, 2);

    // v = x @ w3       (M=1024, N=512, K=512) -> split bf16
    hmma_gemm<false, true><<<gBig, blk, 3 * 53248>>>(
        xh, xl, wh[2], wl[2], nullptr, vh, vl, DD, DD, DD, strND, strDD, strND, NBE, DE, 16, 2);

    // T = G @ w2       (M=512, N=512, K=512) -> split bf16
    hmma_gemm<false, true><<<gSml, blk, 3 * 53248>>>(
        Gh, Gl, wh[1], wl[1], nullptr, Th, Tl, DD, DD, DD, strDD, strDD, strDD, NBE, DE, 16, 2);

    // atten = w1^T @ T (M=512, N=512, K=512) -> fp32
    hmma_gemm<true, false><<<gSml, blk, 3 * 49152>>>(
        wh[0], wl[0], Th, Tl, att, nullptr, nullptr, DD, DD, DD, strDD, strDD, strDD, DE, NBE, 16, 2);

    // softmax -> split bf16
    softmax_rows<<<NBE * DD, 128>>>(att, (uint32_t*)ath, (uint32_t*)atl);

    // out = v @ att    (M=1024, N=512, K=512) -> fp32
    hmma_gemm<false, false><<<gBig, blk, 3 * 53248>>>(
        vh, vl, ath, atl, out, nullptr, nullptr, DD, DD, DD, strND, strDD, strND, NBE, NBE, 16, 2);
}

// round 16
// speedup vs baseline: 1.6739x; 1.1085x over previous
#include <cuda_runtime.h>
#include <cuda_bf16.h>
#include <cstdint>
#include <cstddef>

#define DB 4
#define DE 16
#define DN 1024
#define DD 512
#define NBE (DB * DE)

typedef __nv_bfloat16 bf16;

// ---------------- scratch (__device__ globals; no allocs allowed) ----------
__device__ __align__(256) bf16 g_xh[(size_t)DB * DE * DN * DD];
__device__ __align__(256) bf16 g_xl[(size_t)DB * DE * DN * DD];
__device__ __align__(256) bf16 g_wh[3][(size_t)DE * DD * DD];
__device__ __align__(256) bf16 g_wl[3][(size_t)DE * DD * DD];
__device__ __align__(256) bf16 g_Gh[(size_t)NBE * DD * DD];
__device__ __align__(256) bf16 g_Gl[(size_t)NBE * DD * DD];
__device__ __align__(256) bf16 g_Th[(size_t)NBE * DD * DD];
__device__ __align__(256) bf16 g_Tl[(size_t)NBE * DD * DD];
__device__ __align__(256) bf16 g_Uh[(size_t)NBE * DD * DD];
__device__ __align__(256) bf16 g_Ul[(size_t)NBE * DD * DD];
__device__ __align__(256) float g_att[(size_t)NBE * DD * DD];
__device__ __align__(256) bf16 g_ah[(size_t)NBE * DD * DD];
__device__ __align__(256) bf16 g_al[(size_t)NBE * DD * DD];

// ---------------- helpers ----------------
__device__ __forceinline__ uint32_t smem_u32(const void* p) {
    uint32_t a;
    asm("{ .reg .u64 t; cvta.to.shared.u64 t, %1; cvt.u32.u64 %0, t; }" : "=r"(a) : "l"(p));
    return a;
}
__device__ __forceinline__ void ldsm4(uint32_t* r, uint32_t addr) {
    asm volatile("ldmatrix.sync.aligned.m8n8.x4.shared.b16 {%0,%1,%2,%3}, [%4];"
                 : "=r"(r[0]), "=r"(r[1]), "=r"(r[2]), "=r"(r[3]) : "r"(addr));
}
__device__ __forceinline__ void ldsm4t(uint32_t* r, uint32_t addr) {
    asm volatile("ldmatrix.sync.aligned.m8n8.x4.trans.shared.b16 {%0,%1,%2,%3}, [%4];"
                 : "=r"(r[0]), "=r"(r[1]), "=r"(r[2]), "=r"(r[3]) : "r"(addr));
}
__device__ __forceinline__ void mma16816(float* d, const uint32_t* a, const uint32_t* b) {
    asm volatile(
        "mma.sync.aligned.m16n8k16.row.col.f32.bf16.bf16.f32 "
        "{%0,%1,%2,%3}, {%4,%5,%6,%7}, {%8,%9}, {%0,%1,%2,%3};"
        : "+f"(d[0]), "+f"(d[1]), "+f"(d[2]), "+f"(d[3])
        : "r"(a[0]), "r"(a[1]), "r"(a[2]), "r"(a[3]), "r"(b[0]), "r"(b[1]));
}
__device__ __forceinline__ void split2(float x, float y, uint32_t& h, uint32_t& l) {
    __nv_bfloat162 hb = __floats2bfloat162_rn(x, y);
    float2 hf = __bfloat1622float2(hb);
    __nv_bfloat162 lb = __floats2bfloat162_rn(x - hf.x, y - hf.y);
    h = reinterpret_cast<uint32_t&>(hb);
    l = reinterpret_cast<uint32_t&>(lb);
}
__device__ __forceinline__ void cpa16(uint32_t dst, const void* src) {
    asm volatile("cp.async.cg.shared.global [%0], [%1], 16;" :: "r"(dst), "l"(src));
}
__device__ __forceinline__ void cpa_commit() {
    asm volatile("cp.async.commit_group;" ::: "memory");
}
template <int N>
__device__ __forceinline__ void cpa_wait() {
    asm volatile("cp.async.wait_group %0;" :: "n"(N) : "memory");
}

// ---------------------------------------------------------------------------
// HMMA bf16-split GEMM, pre-split operands.
// CTA tile 128(M) x 256(N), BK=32, 256 thr, 8 warps (2M x 4N) of 64x64.
// TRANSA=false: A hi/lo row-major M x K (lda) ; SMEM stride-80 layout, ldsm
// TRANSA=true : A hi/lo row-major K x M (lda) ; SMEM K-major 256B rows, ldsm.trans
// B hi/lo row-major K x N (ldb), SMEM 512B rows xor-swizzle, ldsm.trans.
// C: fp32 (Cf) or split hi/lo (Chi/Clo) per OUT_SPLIT.
// Batch: A += (be%modA)*sA ; B += (be%modB)*sB ; C += be*sC
// ---------------------------------------------------------------------------
template <bool TRANSA, bool OUT_SPLIT>
__global__ __launch_bounds__(256, 1) void hmma_gemm(
    const bf16* __restrict__ Ahg, const bf16* __restrict__ Alg,
    const bf16* __restrict__ Bhg, const bf16* __restrict__ Blg,
    float* __restrict__ Cf, bf16* __restrict__ Chi, bf16* __restrict__ Clo,
    int lda, int ldb, int ldc, long sA, long sB, long sC,
    int modA, int modB, int ktiles, int ntile)
{
    constexpr int AH  = 0;
    constexpr int AL  = TRANSA ? 8192 : 10240;
    constexpr int BH  = 2 * AL;
    constexpr int BL  = BH + 16384;
    constexpr int STG = BL + 16384;

    extern __shared__ __align__(1024) char smem[];
    const uint32_t sbase = smem_u32(smem);

    const int t    = threadIdx.x;
    const int lane = t & 31;
    const int wid  = t >> 5;
    const int be   = blockIdx.y;
    const bf16* Ah = Ahg + (size_t)(be % modA) * sA;
    const bf16* Al = Alg + (size_t)(be % modA) * sA;
    const bf16* Bh = Bhg + (size_t)(be % modB) * sB;
    const bf16* Bl = Blg + (size_t)(be % modB) * sB;

    const int m0 = (blockIdx.x / ntile) << 7;
    const int n0 = (blockIdx.x % ntile) << 8;

    // ---- loader maps (cp.async, 16B chunks) ----
    const int lbk = t >> 3;
    const int lbc = (t & 7) << 2;
    const uint32_t bsw = (uint32_t)((lbk & 7) << 4);
    const bf16* BhR = Bh + (size_t)lbk * ldb + n0 + lbc * 8;
    const bf16* BlR = Bl + (size_t)lbk * ldb + n0 + lbc * 8;
    const uint32_t bdst = (uint32_t)lbk * 512u;
    const int lak = t >> 3;            // TRANSA: k row
    const int lac = (t & 7) << 1;      // TRANSA: chunks (2) of 16 (256B row)
    const int lam = t >> 1;            // !TRANSA: m row
    const int lkc = (t & 1) << 1;      // !TRANSA: chunks (2)
    const bf16* AhR;
    const bf16* AlR;
    uint32_t adst0, adst1;
    if (TRANSA) {
        AhR = Ah + (size_t)lak * lda + m0 + lac * 8;
        AlR = Al + (size_t)lak * lda + m0 + lac * 8;
        const uint32_t asw = (uint32_t)((lak & 7) << 4);
        adst0 = (uint32_t)lak * 256u + (((uint32_t)(lac * 16)) ^ asw);
        adst1 = (uint32_t)lak * 256u + (((uint32_t)((lac + 1) * 16)) ^ asw);
    } else {
        AhR = Ah + (size_t)(m0 + lam) * lda + lkc * 8;
        AlR = Al + (size_t)(m0 + lam) * lda + lkc * 8;
        adst0 = (uint32_t)lam * 80u + (uint32_t)(lkc * 16);
        adst1 = adst0 + 16u;
    }
    const int astep = TRANSA ? 32 * lda : 32;
    const int bstep = 32 * ldb;

    // ---- compute maps (warp 64x64) ----
    const int mw = (wid >> 2) << 6;
    const int nw = (wid & 3) << 6;
    const uint32_t a_off = (uint32_t)(mw + (lane & 15)) * 80u + ((lane >> 4) << 4);
    const int kl = (lane & 7) | ((lane >> 4) << 3);
    const int mbit = (lane >> 3) & 1;
    const uint32_t atsw = (uint32_t)((kl & 7) << 4);
    const int bkl = lane & 15;
    const int bnl = (lane >> 4) << 3;
    uint32_t b_off[4];
#pragma unroll
    for (int njp = 0; njp < 4; njp++)
        b_off[njp] = (uint32_t)bkl * 512u +
                     ((uint32_t)((nw + njp * 16 + bnl) << 1) ^ (uint32_t)((bkl & 7) << 4));

    float acc[4][8][4];
#pragma unroll
    for (int i = 0; i < 4; i++)
#pragma unroll
        for (int j = 0; j < 8; j++)
#pragma unroll
            for (int r = 0; r < 4; r++) acc[i][j][r] = 0.0f;

    auto issue = [&](int s, int kt) {
        const uint32_t sb = sbase + (uint32_t)(s * STG);
        const bf16* bh = BhR + (size_t)kt * bstep;
        const bf16* bl = BlR + (size_t)kt * bstep;
#pragma unroll
        for (int c = 0; c < 4; c++) {
            const uint32_t d = sb + BH + bdst + (((uint32_t)((lbc + c) * 16)) ^ bsw);
            cpa16(d, bh + c * 8);
            cpa16(d + (BL - BH), bl + c * 8);
        }
        const bf16* ah = AhR + (size_t)kt * astep;
        const bf16* al = AlR + (size_t)kt * astep;
        cpa16(sb + AH + adst0, ah);
        cpa16(sb + AH + adst1, ah + 8);
        cpa16(sb + AL + adst0, al);
        cpa16(sb + AL + adst1, al + 8);
    };

    issue(0, 0); cpa_commit();
    issue(1, 1); cpa_commit();

    int s = 0;
    for (int kt = 0; kt < ktiles; kt++) {
        if (kt + 2 < ktiles) {
            int s2 = s + 2; if (s2 >= 3) s2 -= 3;
            issue(s2, kt + 2); cpa_commit();
            cpa_wait<2>();
        } else if (kt + 2 == ktiles) {
            cpa_wait<1>();
        } else {
            cpa_wait<0>();
        }
        __syncthreads();

        const uint32_t sb32 = sbase + (uint32_t)(s * STG);
        const uint32_t ah = sb32 + AH, al = sb32 + AL;
        const uint32_t bh = sb32 + BH, bl = sb32 + BL;
#pragma unroll
        for (int ks = 0; ks < 2; ks++) {
            uint32_t Afh[4][4], Afl[4][4];
#pragma unroll
            for (int mi = 0; mi < 4; mi++) {
                if (TRANSA) {
                    const uint32_t mcol2 = (uint32_t)((mw + mi * 16 + mbit * 8) << 1);
                    const uint32_t ao = (uint32_t)((ks * 16 + kl) * 256) + (mcol2 ^ atsw);
                    ldsm4t(Afh[mi], ah + ao);
                    ldsm4t(Afl[mi], al + ao);
                } else {
                    const uint32_t ao = a_off + (uint32_t)(mi * 16 * 80) + (uint32_t)(ks * 32);
                    ldsm4(Afh[mi], ah + ao);
                    ldsm4(Afl[mi], al + ao);
                }
            }
#pragma unroll
            for (int njp = 0; njp < 4; njp++) {
                uint32_t Bfh[4], Bfl[4];
                const uint32_t bo = b_off[njp] + (uint32_t)(ks * 16 * 512);
                ldsm4t(Bfh, bh + bo);
                ldsm4t(Bfl, bl + bo);
#pragma unroll
                for (int mi = 0; mi < 4; mi++)
#pragma unroll
                    for (int j = 0; j < 2; j++) {
                        float* d = acc[mi][njp * 2 + j];
                        mma16816(d, Afh[mi], &Bfh[2 * j]);  // hi*hi
                        mma16816(d, Afh[mi], &Bfl[2 * j]);  // hi*lo
                        mma16816(d, Afl[mi], &Bfh[2 * j]);  // lo*hi
                    }
            }
        }
        __syncthreads();
        if (++s == 3) s = 0;
    }

    // ---- epilogue ----
    const int cm = m0 + mw + (lane >> 2);
    const int cn = n0 + nw + ((lane & 3) << 1);
#pragma unroll
    for (int mi = 0; mi < 4; mi++) {
#pragma unroll
        for (int nj = 0; nj < 8; nj++) {
            float* d = acc[mi][nj];
            const size_t i0 = (size_t)(cm + mi * 16) * ldc + cn + nj * 8 + (size_t)be * sC;
            const size_t i1 = i0 + (size_t)8 * ldc;
            if (OUT_SPLIT) {
                uint32_t h0, l0, h1, l1;
                split2(d[0], d[1], h0, l0);
                split2(d[2], d[3], h1, l1);
                *(uint32_t*)(Chi + i0) = h0;
                *(uint32_t*)(Clo + i0) = l0;
                *(uint32_t*)(Chi + i1) = h1;
                *(uint32_t*)(Clo + i1) = l1;
            } else {
                Cf[i0] = d[0]; Cf[i0 + 1] = d[1];
                Cf[i1] = d[2]; Cf[i1 + 1] = d[3];
            }
        }
    }
}

// ---------------------------------------------------------------------------
// fp32 -> bf16 hi/lo elementwise split
// ---------------------------------------------------------------------------
__global__ void split_conv(const float4* __restrict__ in,
                           uint32_t* __restrict__ hi, uint32_t* __restrict__ lo, int n4)
{
    const int i = blockIdx.x * blockDim.x + threadIdx.x;
    if (i >= n4) return;
    float4 v = in[i];
    uint32_t h0, l0, h1, l1;
    split2(v.x, v.y, h0, l0);
    split2(v.z, v.w, h1, l1);
    hi[2 * i] = h0; hi[2 * i + 1] = h1;
    lo[2 * i] = l0; lo[2 * i + 1] = l1;
}

// ---------------------------------------------------------------------------
// Row softmax over last dim (512) -> writes bf16 hi/lo
// ---------------------------------------------------------------------------
__global__ void softmax_rows(const float* __restrict__ att,
                             uint32_t* __restrict__ ah, uint32_t* __restrict__ al)
{
    __shared__ float smax[4];
    __shared__ float ssum[4];
    const int row = blockIdx.x;
    const float4* p = (const float4*)(att + (size_t)row * DD);
    const int t = threadIdx.x;

    float4 v = p[t];
    float m = fmaxf(fmaxf(v.x, v.y), fmaxf(v.z, v.w));
#pragma unroll
    for (int o = 16; o > 0; o >>= 1) m = fmaxf(m, __shfl_xor_sync(0xffffffffu, m, o));
    if ((t & 31) == 0) smax[t >> 5] = m;
    __syncthreads();
    m = fmaxf(fmaxf(smax[0], smax[1]), fmaxf(smax[2], smax[3]));

    v.x = expf(v.x - m); v.y = expf(v.y - m);
    v.z = expf(v.z - m); v.w = expf(v.w - m);
    float s = v.x + v.y + v.z + v.w;
#pragma unroll
    for (int o = 16; o > 0; o >>= 1) s += __shfl_xor_sync(0xffffffffu, s, o);
    if ((t & 31) == 0) ssum[t >> 5] = s;
    __syncthreads();
    s = ssum[0] + ssum[1] + ssum[2] + ssum[3];

    const float inv = 1.0f / s;
    uint32_t h0, l0, h1, l1;
    split2(v.x * inv, v.y * inv, h0, l0);
    split2(v.z * inv, v.w * inv, h1, l1);
    const size_t o2 = (size_t)row * (DD / 2) + 2 * t;
    ah[o2] = h0; ah[o2 + 1] = h1;
    al[o2] = l0; al[o2 + 1] = l1;
}

extern "C" void kernel_launch(void* const* d_in, const int* in_sizes, int n_in,
                              void* d_out, int out_size)
{
    (void)in_sizes; (void)n_in; (void)out_size;
    const float* x  = (const float*)d_in[0];
    const float* w1 = (const float*)d_in[1];
    const float* w2 = (const float*)d_in[2];
    const float* w3 = (const float*)d_in[3];
    float* out = (float*)d_out;

    bf16 *xh, *xl, *wh0, *wl0, *Gh, *Gl, *Th, *Tl, *Uh, *Ul, *ath, *atl;
    float* att;
    cudaGetSymbolAddress((void**)&xh, g_xh);
    cudaGetSymbolAddress((void**)&xl, g_xl);
    cudaGetSymbolAddress((void**)&wh0, g_wh);
    cudaGetSymbolAddress((void**)&wl0, g_wl);
    cudaGetSymbolAddress((void**)&Gh, g_Gh);
    cudaGetSymbolAddress((void**)&Gl, g_Gl);
    cudaGetSymbolAddress((void**)&Th, g_Th);
    cudaGetSymbolAddress((void**)&Tl, g_Tl);
    cudaGetSymbolAddress((void**)&Uh, g_Uh);
    cudaGetSymbolAddress((void**)&Ul, g_Ul);
    cudaGetSymbolAddress((void**)&att, g_att);
    cudaGetSymbolAddress((void**)&ath, g_ah);
    cudaGetSymbolAddress((void**)&atl, g_al);

    const size_t WSZ = (size_t)DE * DD * DD;
    bf16* wh[3] = {wh0, wh0 + WSZ, wh0 + 2 * WSZ};
    bf16* wl[3] = {wl0, wl0 + WSZ, wl0 + 2 * WSZ};

    cudaFuncSetAttribute(hmma_gemm<false, true>,  cudaFuncAttributeMaxDynamicSharedMemorySize, 3 * 53248);
    cudaFuncSetAttribute(hmma_gemm<false, false>, cudaFuncAttributeMaxDynamicSharedMemorySize, 3 * 53248);
    cudaFuncSetAttribute(hmma_gemm<true, false>,  cudaFuncAttributeMaxDynamicSharedMemorySize, 3 * 49152);
    cudaFuncSetAttribute(hmma_gemm<true, true>,   cudaFuncAttributeMaxDynamicSharedMemorySize, 3 * 49152);

    // ---- pre-split x and weights ----
    {
        const int n4x = (DB * DE * DN * DD) / 4;
        split_conv<<<(n4x + 255) / 256, 256>>>((const float4*)x, (uint32_t*)xh, (uint32_t*)xl, n4x);
        const int n4w = (DE * DD * DD) / 4;
        split_conv<<<(n4w + 255) / 256, 256>>>((const float4*)w1, (uint32_t*)wh[0], (uint32_t*)wl[0], n4w);
        split_conv<<<(n4w + 255) / 256, 256>>>((const float4*)w2, (uint32_t*)wh[1], (uint32_t*)wl[1], n4w);
        split_conv<<<(n4w + 255) / 256, 256>>>((const float4*)w3, (uint32_t*)wh[2], (uint32_t*)wl[2], n4w);
    }

    const long strND = (long)DN * DD;
    const long strDD = (long)DD * DD;

    dim3 blk(256);
    dim3 gBig(16, NBE);    // M=1024: (1024/128)*(512/256)
    dim3 gSml(8,  NBE);    // M=512 : (512/128)*(512/256)

    // G = x^T x        (M=512, N=512, K=1024) -> split bf16
    hmma_gemm<true, true><<<gSml, blk, 3 * 49152>>>(
        xh, xl, xh, xl, nullptr, Gh, Gl, DD, DD, DD, strND, strND, strDD, NBE, NBE, 32, 2);

    // T = G @ w2       (M=512, N=512, K=512) -> split bf16
    hmma_gemm<false, true><<<gSml, blk, 3 * 53248>>>(
        Gh, Gl, wh[1], wl[1], nullptr, Th, Tl, DD, DD, DD, strDD, strDD, strDD, NBE, DE, 16, 2);

    // atten = w1^T @ T (M=512, N=512, K=512) -> fp32
    hmma_gemm<true, false><<<gSml, blk, 3 * 49152>>>(
        wh[0], wl[0], Th, Tl, att, nullptr, nullptr, DD, DD, DD, strDD, strDD, strDD, DE, NBE, 16, 2);

    // softmax -> split bf16
    softmax_rows<<<NBE * DD, 128>>>(att, (uint32_t*)ath, (uint32_t*)atl);

    // U = w3 @ att     (M=512, N=512, K=512) -> split bf16
    hmma_gemm<false, true><<<gSml, blk, 3 * 53248>>>(
        wh[2], wl[2], ath, atl, nullptr, Uh, Ul, DD, DD, DD, strDD, strDD, strDD, DE, NBE, 16, 2);

    // out = x @ U      (M=1024, N=512, K=512) -> fp32
    hmma_gemm<false, false><<<gBig, blk, 3 * 53248>>>(
        xh, xl, Uh, Ul, out, nullptr, nullptr, DD, DD, DD, strND, strDD, strND, NBE, NBE, 16, 2);
}